// round 14
// baseline (speedup 1.0000x reference)
#include <cuda_runtime.h>
#include <cuda_bf16.h>
#include <cstdint>
#include <math.h>

// ---------------------------------------------------------------------------
// PubMedGAT round 13:
//  - agg1/agg2: unrolled gather (2-way / 4-way) for higher MLP
//  - enqueue order: chain A first so ncu -s5 captures GEMM1
//  - otherwise identical to round 12
// ---------------------------------------------------------------------------

#define N_NODES 50000
#define N_EDGES 800000
#define IN_DIM  512
#define HEADS   4
#define HID     64
#define F1DIM   (HEADS*HID)   // 256
#define OUTD    64
#define NEG_SLOPE 0.2f
#define SCAN_NB ((N_NODES + 255) / 256)   // 196

// ------------------------- scratch (device globals) -------------------------
__device__ float          g_f1  [N_NODES * F1DIM];
__device__ __nv_bfloat16  g_a1hi[N_NODES * IN_DIM];
__device__ __nv_bfloat16  g_a1lo[N_NODES * IN_DIM];
__device__ __nv_bfloat16  g_h1hi[N_NODES * F1DIM];
__device__ __nv_bfloat16  g_h1lo[N_NODES * F1DIM];
__device__ float          g_f2  [N_NODES * OUTD];
__device__ float          g_el1 [N_NODES * HEADS];
__device__ float          g_er1 [N_NODES * HEADS];
__device__ float          g_el2 [N_NODES];
__device__ float          g_er2 [N_NODES];
__device__ int            g_cnt [N_NODES + 1];
__device__ int            g_cursor[N_NODES];
__device__ int            g_csr_src[N_EDGES];
__device__ int            g_partial[N_NODES];
__device__ int            g_bsum[SCAN_NB];
__device__ int            g_boff[SCAN_NB];
__device__ __nv_bfloat16  g_w1hi[F1DIM * IN_DIM];
__device__ __nv_bfloat16  g_w1lo[F1DIM * IN_DIM];
__device__ __nv_bfloat16  g_w2hi[OUTD * F1DIM];
__device__ __nv_bfloat16  g_w2lo[OUTD * F1DIM];

// ------------------------------ helpers -------------------------------------
__device__ __forceinline__ uint32_t smem_to_u32(const void* p) {
    uint32_t a;
    asm("{ .reg .u64 t; cvta.to.shared.u64 t, %1; cvt.u32.u64 %0, t; }"
        : "=r"(a) : "l"(p));
    return a;
}
__device__ __forceinline__ void ldm_x4(unsigned* r, uint32_t addr) {
    asm volatile("ldmatrix.sync.aligned.m8n8.x4.shared.b16 {%0,%1,%2,%3}, [%4];"
                 : "=r"(r[0]), "=r"(r[1]), "=r"(r[2]), "=r"(r[3]) : "r"(addr));
}
__device__ __forceinline__ void mma16816(float* c, const unsigned* a,
                                         const unsigned* b) {
    asm volatile(
        "mma.sync.aligned.m16n8k16.row.col.f32.bf16.bf16.f32 "
        "{%0,%1,%2,%3}, {%4,%5,%6,%7}, {%8,%9}, {%0,%1,%2,%3};"
        : "+f"(c[0]), "+f"(c[1]), "+f"(c[2]), "+f"(c[3])
        : "r"(a[0]), "r"(a[1]), "r"(a[2]), "r"(a[3]), "r"(b[0]), "r"(b[1]));
}
__device__ __forceinline__ unsigned pk2(__nv_bfloat16 a, __nv_bfloat16 b) {
    unsigned short ua = __bfloat16_as_ushort(a);
    unsigned short ub = __bfloat16_as_ushort(b);
    return (unsigned)ua | ((unsigned)ub << 16);
}
__device__ __forceinline__ float lrelu(float x) {
    return x >= 0.0f ? x : NEG_SLOPE * x;
}
__device__ __forceinline__ float warp_max(float v) {
#pragma unroll
    for (int o = 16; o > 0; o >>= 1)
        v = fmaxf(v, __shfl_xor_sync(0xFFFFFFFFu, v, o));
    return v;
}
__device__ __forceinline__ float warp_sum(float v) {
#pragma unroll
    for (int o = 16; o > 0; o >>= 1)
        v += __shfl_xor_sync(0xFFFFFFFFu, v, o);
    return v;
}

// ------------------------------ CSR build -----------------------------------
__global__ void init_kernel() {
    int i = blockIdx.x * blockDim.x + threadIdx.x;
    if (i <= N_NODES) g_cnt[i] = 0;
}
__global__ void hist_kernel(const int* __restrict__ dst) {
    int e = blockIdx.x * blockDim.x + threadIdx.x;
    if (e < N_EDGES) atomicAdd(&g_cnt[dst[e]], 1);
}
__global__ void scanA_kernel() {
    __shared__ int sm[256];
    const int t = threadIdx.x;
    const int i = blockIdx.x * 256 + t;
    int c = (i < N_NODES) ? g_cnt[i] : 0;
    sm[t] = c;
    __syncthreads();
    for (int off = 1; off < 256; off <<= 1) {
        int u = (t >= off) ? sm[t - off] : 0;
        __syncthreads();
        sm[t] += u;
        __syncthreads();
    }
    if (i < N_NODES) g_partial[i] = sm[t] - c;
    if (t == 255) g_bsum[blockIdx.x] = sm[255];
}
__global__ void scanB_kernel() {
    __shared__ int sm[256];
    const int t = threadIdx.x;
    int v = (t < SCAN_NB) ? g_bsum[t] : 0;
    sm[t] = v;
    __syncthreads();
    for (int off = 1; off < 256; off <<= 1) {
        int u = (t >= off) ? sm[t - off] : 0;
        __syncthreads();
        sm[t] += u;
        __syncthreads();
    }
    if (t < SCAN_NB) g_boff[t] = sm[t] - v;
    if (t == SCAN_NB - 1) g_cnt[N_NODES] = sm[t];
}
__global__ void scanC_kernel() {
    int i = blockIdx.x * blockDim.x + threadIdx.x;
    if (i >= N_NODES) return;
    int off = g_partial[i] + g_boff[i >> 8];
    g_cnt[i] = off;
    g_cursor[i] = off;
}
__global__ void fill_kernel(const int* __restrict__ src,
                            const int* __restrict__ dst) {
    int e = blockIdx.x * blockDim.x + threadIdx.x;
    if (e >= N_EDGES) return;
    int d = dst[e];
    int pos = atomicAdd(&g_cursor[d], 1);
    g_csr_src[pos] = src[e];
}

// ------------------------- split kernels -------------------------------------
__global__ void asplit_kernel(const float* __restrict__ A,
                              __nv_bfloat16* __restrict__ hi,
                              __nv_bfloat16* __restrict__ lo,
                              int total4) {
    int i = blockIdx.x * blockDim.x + threadIdx.x;
    if (i >= total4) return;
    float4 v = ((const float4*)A)[i];
    __nv_bfloat16 hx = __float2bfloat16(v.x), hy = __float2bfloat16(v.y);
    __nv_bfloat16 hz = __float2bfloat16(v.z), hw = __float2bfloat16(v.w);
    ((uint2*)hi)[i] = make_uint2(pk2(hx, hy), pk2(hz, hw));
    ((uint2*)lo)[i] = make_uint2(
        pk2(__float2bfloat16(v.x - __bfloat162float(hx)),
            __float2bfloat16(v.y - __bfloat162float(hy))),
        pk2(__float2bfloat16(v.z - __bfloat162float(hz)),
            __float2bfloat16(v.w - __bfloat162float(hw))));
}

__global__ void wsplit_kernel(const float* __restrict__ W,
                              __nv_bfloat16* __restrict__ hi,
                              __nv_bfloat16* __restrict__ lo,
                              int K, int N) {
    int i = blockIdx.x * blockDim.x + threadIdx.x;
    if (i >= K * N) return;
    int k = i / N, n = i % N;
    float v = W[i];
    __nv_bfloat16 h = __float2bfloat16(v);
    hi[(size_t)n * K + k] = h;
    lo[(size_t)n * K + k] = __float2bfloat16(v - __bfloat162float(h));
}

// --------------------- mma.sync split-bf16 GEMM ------------------------------
template<int BN, int KTOT, bool FELR, bool FELR2>
__global__ void __launch_bounds__(256)
gemm_mma(const __nv_bfloat16* __restrict__ Ahi,
         const __nv_bfloat16* __restrict__ Alo,
         const __nv_bfloat16* __restrict__ Bhi,
         const __nv_bfloat16* __restrict__ Blo,
         float* __restrict__ C, int M, int NTOT,
         const float* __restrict__ alv_g, const float* __restrict__ arv_g) {
    constexpr int WN = BN / 2;
    constexpr int NA = WN / 8;
    constexpr int ROWB = 144;
    constexpr int AH = 0;
    constexpr int AL = 128 * ROWB;
    constexpr int BH = 2 * 128 * ROWB;
    constexpr int BL = BH + BN * ROWB;

    extern __shared__ char smem[];
    const uint32_t sb = smem_to_u32(smem);
    const int tid = threadIdx.x;
    const int wid = tid >> 5, lane = tid & 31;
    const int wr = wid >> 1, wc = wid & 1;
    const int bm = blockIdx.x * 128;
    const int bn = blockIdx.y * BN;

    float acc[2][NA][4];
#pragma unroll
    for (int i = 0; i < 2; i++)
#pragma unroll
        for (int j = 0; j < NA; j++)
#pragma unroll
            for (int k = 0; k < 4; k++) acc[i][j][k] = 0.f;

    const int a_row = ((lane >> 3) & 1) * 8 + (lane & 7);
    const int a_col = (lane >> 4) * 8;
    const int b_row = ((lane >> 4) & 1) * 8 + (lane & 7);
    const int b_col = ((lane >> 3) & 1) * 8;

    for (int kc = 0; kc < KTOT / 64; kc++) {
#pragma unroll
        for (int i = 0; i < 4; i++) {
            int idx = tid + i * 256;
            int r = idx >> 3, c = idx & 7;
            int grow = bm + r;
            uint4 vh = make_uint4(0, 0, 0, 0), vl = make_uint4(0, 0, 0, 0);
            if (grow < M) {
                size_t g = (size_t)grow * KTOT + kc * 64 + c * 8;
                vh = *(const uint4*)&Ahi[g];
                vl = *(const uint4*)&Alo[g];
            }
            *(uint4*)(smem + AH + r * ROWB + c * 16) = vh;
            *(uint4*)(smem + AL + r * ROWB + c * 16) = vl;
        }
#pragma unroll
        for (int i = 0; i < BN / 32; i++) {
            int idx = tid + i * 256;
            int r = idx >> 3, c = idx & 7;
            size_t g = (size_t)(bn + r) * KTOT + kc * 64 + c * 8;
            *(uint4*)(smem + BH + r * ROWB + c * 16) = *(const uint4*)&Bhi[g];
            *(uint4*)(smem + BL + r * ROWB + c * 16) = *(const uint4*)&Blo[g];
        }
        __syncthreads();

#pragma unroll
        for (int kk = 0; kk < 4; kk++) {
            unsigned ah[2][4], al[2][4], bh[NA][2], bl[NA][2];
#pragma unroll
            for (int i = 0; i < 2; i++) {
                uint32_t ad = sb + (wr * 32 + i * 16 + a_row) * ROWB
                            + (kk * 16 + a_col) * 2;
                ldm_x4(ah[i], ad + AH);
                ldm_x4(al[i], ad + AL);
            }
#pragma unroll
            for (int p = 0; p < NA / 2; p++) {
                uint32_t bd = sb + (wc * WN + p * 16 + b_row) * ROWB
                            + (kk * 16 + b_col) * 2;
                unsigned t[4];
                ldm_x4(t, bd + BH);
                bh[2 * p][0] = t[0]; bh[2 * p][1] = t[1];
                bh[2 * p + 1][0] = t[2]; bh[2 * p + 1][1] = t[3];
                ldm_x4(t, bd + BL);
                bl[2 * p][0] = t[0]; bl[2 * p][1] = t[1];
                bl[2 * p + 1][0] = t[2]; bl[2 * p + 1][1] = t[3];
            }
#pragma unroll
            for (int i = 0; i < 2; i++)
#pragma unroll
                for (int j = 0; j < NA; j++) {
                    mma16816(acc[i][j], ah[i], bh[j]);
                    mma16816(acc[i][j], al[i], bh[j]);
                    mma16816(acc[i][j], ah[i], bl[j]);
                }
        }
        __syncthreads();
    }

#pragma unroll
    for (int i = 0; i < 2; i++) {
        int row = bm + wr * 32 + i * 16 + (lane >> 2);
#pragma unroll
        for (int j = 0; j < NA; j++) {
            int col = bn + wc * WN + j * 8 + (lane & 3) * 2;
            if (row < M)
                *(float2*)&C[(size_t)row * NTOT + col] =
                    make_float2(acc[i][j][0], acc[i][j][1]);
            if (row + 8 < M)
                *(float2*)&C[(size_t)(row + 8) * NTOT + col] =
                    make_float2(acc[i][j][2], acc[i][j][3]);
        }
    }

    if constexpr (FELR) {
        const int head = blockIdx.y * 2 + wc;
        float2 alv[NA], arv[NA];
#pragma unroll
        for (int j = 0; j < NA; j++) {
            int col = bn + wc * WN + j * 8 + (lane & 3) * 2;
            alv[j] = *(const float2*)&alv_g[col];
            arv[j] = *(const float2*)&arv_g[col];
        }
#pragma unroll
        for (int i = 0; i < 2; i++) {
            float el0 = 0.f, el8 = 0.f, er0 = 0.f, er8 = 0.f;
#pragma unroll
            for (int j = 0; j < NA; j++) {
                el0 += acc[i][j][0] * alv[j].x + acc[i][j][1] * alv[j].y;
                er0 += acc[i][j][0] * arv[j].x + acc[i][j][1] * arv[j].y;
                el8 += acc[i][j][2] * alv[j].x + acc[i][j][3] * alv[j].y;
                er8 += acc[i][j][2] * arv[j].x + acc[i][j][3] * arv[j].y;
            }
#pragma unroll
            for (int o = 1; o < 4; o <<= 1) {
                el0 += __shfl_xor_sync(0xFFFFFFFFu, el0, o);
                el8 += __shfl_xor_sync(0xFFFFFFFFu, el8, o);
                er0 += __shfl_xor_sync(0xFFFFFFFFu, er0, o);
                er8 += __shfl_xor_sync(0xFFFFFFFFu, er8, o);
            }
            int row = bm + wr * 32 + i * 16 + (lane >> 2);
            if ((lane & 3) == 0) {
                if (row < M) {
                    g_el1[row * 4 + head] = el0;
                    g_er1[row * 4 + head] = er0;
                }
                if (row + 8 < M) {
                    g_el1[(row + 8) * 4 + head] = el8;
                    g_er1[(row + 8) * 4 + head] = er8;
                }
            }
        }
    }

    if constexpr (FELR2) {
        float* pe = (float*)smem;
        float2 alv[NA], arv[NA];
#pragma unroll
        for (int j = 0; j < NA; j++) {
            int col = wc * WN + j * 8 + (lane & 3) * 2;
            alv[j] = *(const float2*)&alv_g[col];
            arv[j] = *(const float2*)&arv_g[col];
        }
#pragma unroll
        for (int i = 0; i < 2; i++) {
            float el0 = 0.f, el8 = 0.f, er0 = 0.f, er8 = 0.f;
#pragma unroll
            for (int j = 0; j < NA; j++) {
                el0 += acc[i][j][0] * alv[j].x + acc[i][j][1] * alv[j].y;
                er0 += acc[i][j][0] * arv[j].x + acc[i][j][1] * arv[j].y;
                el8 += acc[i][j][2] * alv[j].x + acc[i][j][3] * alv[j].y;
                er8 += acc[i][j][2] * arv[j].x + acc[i][j][3] * arv[j].y;
            }
#pragma unroll
            for (int o = 1; o < 4; o <<= 1) {
                el0 += __shfl_xor_sync(0xFFFFFFFFu, el0, o);
                el8 += __shfl_xor_sync(0xFFFFFFFFu, el8, o);
                er0 += __shfl_xor_sync(0xFFFFFFFFu, er0, o);
                er8 += __shfl_xor_sync(0xFFFFFFFFu, er8, o);
            }
            if ((lane & 3) == 0) {
                int lr = wr * 32 + i * 16 + (lane >> 2);
                pe[wc * 128 + lr]             = el0;
                pe[wc * 128 + lr + 8]         = el8;
                pe[256 + wc * 128 + lr]       = er0;
                pe[256 + wc * 128 + lr + 8]   = er8;
            }
        }
        __syncthreads();
        if (tid < 128) {
            int row = bm + tid;
            if (row < M) {
                g_el2[row] = pe[tid] + pe[128 + tid];
                g_er2[row] = pe[256 + tid] + pe[384 + tid];
            }
        }
    }
}

// ----- layer-1 aggregation: warp per dst, single-pass, 2-way gather ----------
__global__ void agg1_kernel(const float* __restrict__ b1) {
    __shared__ float sm_a[8][128];
    __shared__ int   sm_s[8][32];
    const int wid = threadIdx.x >> 5;
    const int lane = threadIdx.x & 31;
    const int d = blockIdx.x * 8 + wid;
    if (d >= N_NODES) return;
    const int start = g_cnt[d];
    const int end   = g_cnt[d + 1];

    float4 er = *(const float4*)&g_er1[d * 4];
    const int hh = lane >> 3;

    float m0 = -INFINITY, m1 = -INFINITY, m2 = -INFINITY, m3 = -INFINITY;
    float q0 = 0.f, q1 = 0.f, q2 = 0.f, q3 = 0.f;
    float acc0 = 0.f, acc1 = 0.f, acc2 = 0.f, acc3 = 0.f;
    float acc4 = 0.f, acc5 = 0.f, acc6 = 0.f, acc7 = 0.f;

    for (int base = start; base < end; base += 32) {
        int ei = base + lane;
        float e0 = -INFINITY, e1 = -INFINITY, e2 = -INFINITY, e3 = -INFINITY;
        if (ei < end) {
            int s = g_csr_src[ei];
            float4 el = *(const float4*)&g_el1[s * 4];
            e0 = lrelu(el.x + er.x);
            e1 = lrelu(el.y + er.y);
            e2 = lrelu(el.z + er.z);
            e3 = lrelu(el.w + er.w);
            sm_s[wid][lane] = s;
        }
        float n0 = fmaxf(m0, warp_max(e0));
        float n1 = fmaxf(m1, warp_max(e1));
        float n2 = fmaxf(m2, warp_max(e2));
        float n3 = fmaxf(m3, warp_max(e3));
        float r0 = (m0 >= n0) ? 1.f : __expf(m0 - n0);
        float r1 = (m1 >= n1) ? 1.f : __expf(m1 - n1);
        float r2 = (m2 >= n2) ? 1.f : __expf(m2 - n2);
        float r3 = (m3 >= n3) ? 1.f : __expf(m3 - n3);
        float w0 = __expf(e0 - n0);
        float w1 = __expf(e1 - n1);
        float w2 = __expf(e2 - n2);
        float w3 = __expf(e3 - n3);
        m0 = n0; m1 = n1; m2 = n2; m3 = n3;
        q0 = q0 * r0 + w0;
        q1 = q1 * r1 + w1;
        q2 = q2 * r2 + w2;
        q3 = q3 * r3 + w3;
        sm_a[wid][lane * 4 + 0] = w0;
        sm_a[wid][lane * 4 + 1] = w1;
        sm_a[wid][lane * 4 + 2] = w2;
        sm_a[wid][lane * 4 + 3] = w3;
        __syncwarp();
        float rf = (hh == 0) ? r0 : (hh == 1) ? r1 : (hh == 2) ? r2 : r3;
        acc0 *= rf; acc1 *= rf; acc2 *= rf; acc3 *= rf;
        acc4 *= rf; acc5 *= rf; acc6 *= rf; acc7 *= rf;
        int cnt = min(32, end - base);
        int j = 0;
        for (; j + 2 <= cnt; j += 2) {
            int s0 = sm_s[wid][j];
            int s1 = sm_s[wid][j + 1];
            float a0 = sm_a[wid][(j << 2) | hh];
            float a1 = sm_a[wid][((j + 1) << 2) | hh];
            const float4* fp0 = (const float4*)&g_f1[(size_t)s0 * F1DIM + lane * 8];
            const float4* fp1 = (const float4*)&g_f1[(size_t)s1 * F1DIM + lane * 8];
            float4 u0 = fp0[0], v0 = fp0[1];
            float4 u1 = fp1[0], v1 = fp1[1];
            acc0 += a0 * u0.x; acc1 += a0 * u0.y; acc2 += a0 * u0.z; acc3 += a0 * u0.w;
            acc4 += a0 * v0.x; acc5 += a0 * v0.y; acc6 += a0 * v0.z; acc7 += a0 * v0.w;
            acc0 += a1 * u1.x; acc1 += a1 * u1.y; acc2 += a1 * u1.z; acc3 += a1 * u1.w;
            acc4 += a1 * v1.x; acc5 += a1 * v1.y; acc6 += a1 * v1.z; acc7 += a1 * v1.w;
        }
        if (j < cnt) {
            int s = sm_s[wid][j];
            float a = sm_a[wid][(j << 2) | hh];
            const float4* fp = (const float4*)&g_f1[(size_t)s * F1DIM + lane * 8];
            float4 u = fp[0], v = fp[1];
            acc0 += a * u.x; acc1 += a * u.y; acc2 += a * u.z; acc3 += a * u.w;
            acc4 += a * v.x; acc5 += a * v.y; acc6 += a * v.z; acc7 += a * v.w;
        }
        __syncwarp();
    }

    q0 = warp_sum(q0); q1 = warp_sum(q1); q2 = warp_sum(q2); q3 = warp_sum(q3);
    float qs = (hh == 0) ? q0 : (hh == 1) ? q1 : (hh == 2) ? q2 : q3;
    float iv = qs > 0.f ? 1.0f / qs : 0.f;
    acc0 *= iv; acc1 *= iv; acc2 *= iv; acc3 *= iv;
    acc4 *= iv; acc5 *= iv; acc6 *= iv; acc7 *= iv;

    const float* bp = b1 + lane * 8;
    float o[8] = {acc0 + bp[0], acc1 + bp[1], acc2 + bp[2], acc3 + bp[3],
                  acc4 + bp[4], acc5 + bp[5], acc6 + bp[6], acc7 + bp[7]};
#pragma unroll
    for (int c = 0; c < 8; c++) o[c] = o[c] > 0.f ? o[c] : expm1f(o[c]);

    unsigned hv[4], lv[4];
#pragma unroll
    for (int p = 0; p < 4; p++) {
        __nv_bfloat16 h0 = __float2bfloat16(o[2 * p]);
        __nv_bfloat16 h1b = __float2bfloat16(o[2 * p + 1]);
        hv[p] = pk2(h0, h1b);
        lv[p] = pk2(__float2bfloat16(o[2 * p]     - __bfloat162float(h0)),
                    __float2bfloat16(o[2 * p + 1] - __bfloat162float(h1b)));
    }
    size_t off = (size_t)d * F1DIM + lane * 8;
    *(uint4*)&g_h1hi[off] = make_uint4(hv[0], hv[1], hv[2], hv[3]);
    *(uint4*)&g_h1lo[off] = make_uint4(lv[0], lv[1], lv[2], lv[3]);
}

// ----- layer-2 aggregation: warp per dst, single-pass, 4-way gather ----------
__global__ void agg2_kernel(const float* __restrict__ b2,
                            float* __restrict__ out) {
    __shared__ float sm_a[8][32];
    __shared__ int   sm_s[8][32];
    const int wid = threadIdx.x >> 5;
    const int lane = threadIdx.x & 31;
    const int d = blockIdx.x * 8 + wid;
    if (d >= N_NODES) return;
    const int start = g_cnt[d];
    const int end   = g_cnt[d + 1];

    float er = g_er2[d];
    float m = -INFINITY, q = 0.f;
    float accx = 0.f, accy = 0.f;

    for (int base = start; base < end; base += 32) {
        int ei = base + lane;
        float e = -INFINITY;
        if (ei < end) {
            int s = g_csr_src[ei];
            e = lrelu(g_el2[s] + er);
            sm_s[wid][lane] = s;
        }
        float n = fmaxf(m, warp_max(e));
        float r = (m >= n) ? 1.f : __expf(m - n);
        float w = __expf(e - n);
        m = n;
        q = q * r + w;
        sm_a[wid][lane] = w;
        __syncwarp();
        accx *= r; accy *= r;
        int cnt = min(32, end - base);
        int j = 0;
        for (; j + 4 <= cnt; j += 4) {
            int s0 = sm_s[wid][j],     s1 = sm_s[wid][j + 1];
            int s2 = sm_s[wid][j + 2], s3 = sm_s[wid][j + 3];
            float a0 = sm_a[wid][j],     a1 = sm_a[wid][j + 1];
            float a2 = sm_a[wid][j + 2], a3 = sm_a[wid][j + 3];
            float2 f0 = *(const float2*)&g_f2[(size_t)s0 * OUTD + lane * 2];
            float2 f1 = *(const float2*)&g_f2[(size_t)s1 * OUTD + lane * 2];
            float2 f2 = *(const float2*)&g_f2[(size_t)s2 * OUTD + lane * 2];
            float2 f3 = *(const float2*)&g_f2[(size_t)s3 * OUTD + lane * 2];
            accx += a0 * f0.x; accy += a0 * f0.y;
            accx += a1 * f1.x; accy += a1 * f1.y;
            accx += a2 * f2.x; accy += a2 * f2.y;
            accx += a3 * f3.x; accy += a3 * f3.y;
        }
        for (; j < cnt; j++) {
            int s = sm_s[wid][j];
            float a = sm_a[wid][j];
            float2 f = *(const float2*)&g_f2[(size_t)s * OUTD + lane * 2];
            accx += a * f.x;
            accy += a * f.y;
        }
        __syncwarp();
    }

    q = warp_sum(q);
    float iv = q > 0.f ? 1.0f / q : 0.f;
    float2 o = make_float2(accx * iv + b2[lane * 2],
                           accy * iv + b2[lane * 2 + 1]);
    *(float2*)&out[(size_t)d * OUTD + lane * 2] = o;
}

// ------------------------------ launch --------------------------------------
extern "C" void kernel_launch(void* const* d_in, const int* in_sizes, int n_in,
                              void* d_out, int out_size) {
    const float* features = (const float*)d_in[0];
    const float* W1  = (const float*)d_in[1];
    const float* al1 = (const float*)d_in[2];
    const float* ar1 = (const float*)d_in[3];
    const float* b1  = (const float*)d_in[4];
    const float* W2  = (const float*)d_in[5];
    const float* al2 = (const float*)d_in[6];
    const float* ar2 = (const float*)d_in[7];
    const float* b2  = (const float*)d_in[8];
    const int*   src = (const int*)d_in[9];
    const int*   dst = (const int*)d_in[10];
    float* out = (float*)d_out;

    float *p_f1, *p_f2;
    __nv_bfloat16 *p_a1hi, *p_a1lo, *p_h1hi, *p_h1lo;
    __nv_bfloat16 *p_w1hi, *p_w1lo, *p_w2hi, *p_w2lo;
    cudaGetSymbolAddress((void**)&p_f1,   g_f1);
    cudaGetSymbolAddress((void**)&p_f2,   g_f2);
    cudaGetSymbolAddress((void**)&p_a1hi, g_a1hi);
    cudaGetSymbolAddress((void**)&p_a1lo, g_a1lo);
    cudaGetSymbolAddress((void**)&p_h1hi, g_h1hi);
    cudaGetSymbolAddress((void**)&p_h1lo, g_h1lo);
    cudaGetSymbolAddress((void**)&p_w1hi, g_w1hi);
    cudaGetSymbolAddress((void**)&p_w1lo, g_w1lo);
    cudaGetSymbolAddress((void**)&p_w2hi, g_w2hi);
    cudaGetSymbolAddress((void**)&p_w2lo, g_w2lo);

    constexpr int SMEM1 = (2 * 128 + 2 * 128) * 144;  // 73728
    constexpr int SMEM2 = (2 * 128 + 2 * 64) * 144;   // 55296
    cudaFuncSetAttribute((gemm_mma<128, 512, true, false>),
                         cudaFuncAttributeMaxDynamicSharedMemorySize, SMEM1);
    cudaFuncSetAttribute((gemm_mma<64, 256, false, true>),
                         cudaFuncAttributeMaxDynamicSharedMemorySize, SMEM2);

    const int MTILES = (N_NODES + 127) / 128;  // 391

    cudaStream_t s2;
    cudaStreamCreateWithFlags(&s2, cudaStreamNonBlocking);
    cudaEvent_t evFork, evJoin;
    cudaEventCreateWithFlags(&evFork, cudaEventDisableTiming);
    cudaEventCreateWithFlags(&evJoin, cudaEventDisableTiming);

    // fork recorded first: s2's chain depends only on the stream-0 point
    // BEFORE chain A, so both chains still run concurrently.
    cudaEventRecord(evFork, 0);
    cudaStreamWaitEvent(s2, evFork, 0);

    // ---- chain A enqueued FIRST (GEMM1 = 4th launch for ncu capture)
    wsplit_kernel<<<(IN_DIM * F1DIM + 255) / 256, 256>>>(W1, p_w1hi, p_w1lo, IN_DIM, F1DIM);
    wsplit_kernel<<<(F1DIM * OUTD + 255) / 256, 256>>>(W2, p_w2hi, p_w2lo, F1DIM, OUTD);
    asplit_kernel<<<(N_NODES * IN_DIM / 4 + 255) / 256, 256>>>(
        features, p_a1hi, p_a1lo, N_NODES * IN_DIM / 4);
    {
        dim3 grid(MTILES, F1DIM / 128);
        gemm_mma<128, 512, true, false><<<grid, 256, SMEM1>>>(
            p_a1hi, p_a1lo, p_w1hi, p_w1lo, p_f1, N_NODES, F1DIM, al1, ar1);
    }

    // ---- chain B on s2: CSR build (independent; starts at evFork)
    init_kernel<<<(N_NODES + 256) / 256, 256, 0, s2>>>();
    hist_kernel<<<(N_EDGES + 255) / 256, 256, 0, s2>>>(dst);
    scanA_kernel<<<SCAN_NB, 256, 0, s2>>>();
    scanB_kernel<<<1, 256, 0, s2>>>();
    scanC_kernel<<<SCAN_NB, 256, 0, s2>>>();
    fill_kernel<<<(N_EDGES + 255) / 256, 256, 0, s2>>>(src, dst);

    // join
    cudaEventRecord(evJoin, s2);
    cudaStreamWaitEvent(0, evJoin, 0);

    // ---- serial tail
    agg1_kernel<<<(N_NODES + 7) / 8, 256>>>(b1);
    {
        dim3 grid(MTILES, 1);
        gemm_mma<64, 256, false, true><<<grid, 256, SMEM2>>>(
            p_h1hi, p_h1lo, p_w2hi, p_w2lo, p_f2, N_NODES, OUTD, al2, ar2);
    }
    agg2_kernel<<<(N_NODES + 7) / 8, 256>>>(b2, out);
}

// round 17
// speedup vs baseline: 1.2336x; 1.2336x over previous
#include <cuda_runtime.h>
#include <cuda_bf16.h>
#include <cstdint>
#include <math.h>

// ---------------------------------------------------------------------------
// PubMedGAT round 14:
//  - gemm_mma: B-hi/B-lo fragment registers reused (two sub-passes per kk)
//    + __launch_bounds__(256, 2)  => 2 CTAs/SM (was 1, register-capped)
//  - everything else identical to round 13
// ---------------------------------------------------------------------------

#define N_NODES 50000
#define N_EDGES 800000
#define IN_DIM  512
#define HEADS   4
#define HID     64
#define F1DIM   (HEADS*HID)   // 256
#define OUTD    64
#define NEG_SLOPE 0.2f
#define SCAN_NB ((N_NODES + 255) / 256)   // 196

// ------------------------- scratch (device globals) -------------------------
__device__ float          g_f1  [N_NODES * F1DIM];
__device__ __nv_bfloat16  g_a1hi[N_NODES * IN_DIM];
__device__ __nv_bfloat16  g_a1lo[N_NODES * IN_DIM];
__device__ __nv_bfloat16  g_h1hi[N_NODES * F1DIM];
__device__ __nv_bfloat16  g_h1lo[N_NODES * F1DIM];
__device__ float          g_f2  [N_NODES * OUTD];
__device__ float          g_el1 [N_NODES * HEADS];
__device__ float          g_er1 [N_NODES * HEADS];
__device__ float          g_el2 [N_NODES];
__device__ float          g_er2 [N_NODES];
__device__ int            g_cnt [N_NODES + 1];
__device__ int            g_cursor[N_NODES];
__device__ int            g_csr_src[N_EDGES];
__device__ int            g_partial[N_NODES];
__device__ int            g_bsum[SCAN_NB];
__device__ int            g_boff[SCAN_NB];
__device__ __nv_bfloat16  g_w1hi[F1DIM * IN_DIM];
__device__ __nv_bfloat16  g_w1lo[F1DIM * IN_DIM];
__device__ __nv_bfloat16  g_w2hi[OUTD * F1DIM];
__device__ __nv_bfloat16  g_w2lo[OUTD * F1DIM];

// ------------------------------ helpers -------------------------------------
__device__ __forceinline__ uint32_t smem_to_u32(const void* p) {
    uint32_t a;
    asm("{ .reg .u64 t; cvta.to.shared.u64 t, %1; cvt.u32.u64 %0, t; }"
        : "=r"(a) : "l"(p));
    return a;
}
__device__ __forceinline__ void ldm_x4(unsigned* r, uint32_t addr) {
    asm volatile("ldmatrix.sync.aligned.m8n8.x4.shared.b16 {%0,%1,%2,%3}, [%4];"
                 : "=r"(r[0]), "=r"(r[1]), "=r"(r[2]), "=r"(r[3]) : "r"(addr));
}
__device__ __forceinline__ void mma16816(float* c, const unsigned* a,
                                         const unsigned* b) {
    asm volatile(
        "mma.sync.aligned.m16n8k16.row.col.f32.bf16.bf16.f32 "
        "{%0,%1,%2,%3}, {%4,%5,%6,%7}, {%8,%9}, {%0,%1,%2,%3};"
        : "+f"(c[0]), "+f"(c[1]), "+f"(c[2]), "+f"(c[3])
        : "r"(a[0]), "r"(a[1]), "r"(a[2]), "r"(a[3]), "r"(b[0]), "r"(b[1]));
}
__device__ __forceinline__ unsigned pk2(__nv_bfloat16 a, __nv_bfloat16 b) {
    unsigned short ua = __bfloat16_as_ushort(a);
    unsigned short ub = __bfloat16_as_ushort(b);
    return (unsigned)ua | ((unsigned)ub << 16);
}
__device__ __forceinline__ float lrelu(float x) {
    return x >= 0.0f ? x : NEG_SLOPE * x;
}
__device__ __forceinline__ float warp_max(float v) {
#pragma unroll
    for (int o = 16; o > 0; o >>= 1)
        v = fmaxf(v, __shfl_xor_sync(0xFFFFFFFFu, v, o));
    return v;
}
__device__ __forceinline__ float warp_sum(float v) {
#pragma unroll
    for (int o = 16; o > 0; o >>= 1)
        v += __shfl_xor_sync(0xFFFFFFFFu, v, o);
    return v;
}

// ------------------------------ CSR build -----------------------------------
__global__ void init_kernel() {
    int i = blockIdx.x * blockDim.x + threadIdx.x;
    if (i <= N_NODES) g_cnt[i] = 0;
}
__global__ void hist_kernel(const int* __restrict__ dst) {
    int e = blockIdx.x * blockDim.x + threadIdx.x;
    if (e < N_EDGES) atomicAdd(&g_cnt[dst[e]], 1);
}
__global__ void scanA_kernel() {
    __shared__ int sm[256];
    const int t = threadIdx.x;
    const int i = blockIdx.x * 256 + t;
    int c = (i < N_NODES) ? g_cnt[i] : 0;
    sm[t] = c;
    __syncthreads();
    for (int off = 1; off < 256; off <<= 1) {
        int u = (t >= off) ? sm[t - off] : 0;
        __syncthreads();
        sm[t] += u;
        __syncthreads();
    }
    if (i < N_NODES) g_partial[i] = sm[t] - c;
    if (t == 255) g_bsum[blockIdx.x] = sm[255];
}
__global__ void scanB_kernel() {
    __shared__ int sm[256];
    const int t = threadIdx.x;
    int v = (t < SCAN_NB) ? g_bsum[t] : 0;
    sm[t] = v;
    __syncthreads();
    for (int off = 1; off < 256; off <<= 1) {
        int u = (t >= off) ? sm[t - off] : 0;
        __syncthreads();
        sm[t] += u;
        __syncthreads();
    }
    if (t < SCAN_NB) g_boff[t] = sm[t] - v;
    if (t == SCAN_NB - 1) g_cnt[N_NODES] = sm[t];
}
__global__ void scanC_kernel() {
    int i = blockIdx.x * blockDim.x + threadIdx.x;
    if (i >= N_NODES) return;
    int off = g_partial[i] + g_boff[i >> 8];
    g_cnt[i] = off;
    g_cursor[i] = off;
}
__global__ void fill_kernel(const int* __restrict__ src,
                            const int* __restrict__ dst) {
    int e = blockIdx.x * blockDim.x + threadIdx.x;
    if (e >= N_EDGES) return;
    int d = dst[e];
    int pos = atomicAdd(&g_cursor[d], 1);
    g_csr_src[pos] = src[e];
}

// ------------------------- split kernels -------------------------------------
__global__ void asplit_kernel(const float* __restrict__ A,
                              __nv_bfloat16* __restrict__ hi,
                              __nv_bfloat16* __restrict__ lo,
                              int total4) {
    int i = blockIdx.x * blockDim.x + threadIdx.x;
    if (i >= total4) return;
    float4 v = ((const float4*)A)[i];
    __nv_bfloat16 hx = __float2bfloat16(v.x), hy = __float2bfloat16(v.y);
    __nv_bfloat16 hz = __float2bfloat16(v.z), hw = __float2bfloat16(v.w);
    ((uint2*)hi)[i] = make_uint2(pk2(hx, hy), pk2(hz, hw));
    ((uint2*)lo)[i] = make_uint2(
        pk2(__float2bfloat16(v.x - __bfloat162float(hx)),
            __float2bfloat16(v.y - __bfloat162float(hy))),
        pk2(__float2bfloat16(v.z - __bfloat162float(hz)),
            __float2bfloat16(v.w - __bfloat162float(hw))));
}

__global__ void wsplit_kernel(const float* __restrict__ W,
                              __nv_bfloat16* __restrict__ hi,
                              __nv_bfloat16* __restrict__ lo,
                              int K, int N) {
    int i = blockIdx.x * blockDim.x + threadIdx.x;
    if (i >= K * N) return;
    int k = i / N, n = i % N;
    float v = W[i];
    __nv_bfloat16 h = __float2bfloat16(v);
    hi[(size_t)n * K + k] = h;
    lo[(size_t)n * K + k] = __float2bfloat16(v - __bfloat162float(h));
}

// --------------------- mma.sync split-bf16 GEMM ------------------------------
// B-hi and B-lo processed in two sub-passes sharing fragment registers
// (per-accumulator FMA order unchanged: ah*bh, al*bh, ah*bl).
template<int BN, int KTOT, bool FELR, bool FELR2>
__global__ void __launch_bounds__(256, 2)
gemm_mma(const __nv_bfloat16* __restrict__ Ahi,
         const __nv_bfloat16* __restrict__ Alo,
         const __nv_bfloat16* __restrict__ Bhi,
         const __nv_bfloat16* __restrict__ Blo,
         float* __restrict__ C, int M, int NTOT,
         const float* __restrict__ alv_g, const float* __restrict__ arv_g) {
    constexpr int WN = BN / 2;
    constexpr int NA = WN / 8;
    constexpr int ROWB = 144;
    constexpr int AH = 0;
    constexpr int AL = 128 * ROWB;
    constexpr int BH = 2 * 128 * ROWB;
    constexpr int BL = BH + BN * ROWB;

    extern __shared__ char smem[];
    const uint32_t sb = smem_to_u32(smem);
    const int tid = threadIdx.x;
    const int wid = tid >> 5, lane = tid & 31;
    const int wr = wid >> 1, wc = wid & 1;
    const int bm = blockIdx.x * 128;
    const int bn = blockIdx.y * BN;

    float acc[2][NA][4];
#pragma unroll
    for (int i = 0; i < 2; i++)
#pragma unroll
        for (int j = 0; j < NA; j++)
#pragma unroll
            for (int k = 0; k < 4; k++) acc[i][j][k] = 0.f;

    const int a_row = ((lane >> 3) & 1) * 8 + (lane & 7);
    const int a_col = (lane >> 4) * 8;
    const int b_row = ((lane >> 4) & 1) * 8 + (lane & 7);
    const int b_col = ((lane >> 3) & 1) * 8;

    for (int kc = 0; kc < KTOT / 64; kc++) {
#pragma unroll
        for (int i = 0; i < 4; i++) {
            int idx = tid + i * 256;
            int r = idx >> 3, c = idx & 7;
            int grow = bm + r;
            uint4 vh = make_uint4(0, 0, 0, 0), vl = make_uint4(0, 0, 0, 0);
            if (grow < M) {
                size_t g = (size_t)grow * KTOT + kc * 64 + c * 8;
                vh = *(const uint4*)&Ahi[g];
                vl = *(const uint4*)&Alo[g];
            }
            *(uint4*)(smem + AH + r * ROWB + c * 16) = vh;
            *(uint4*)(smem + AL + r * ROWB + c * 16) = vl;
        }
#pragma unroll
        for (int i = 0; i < BN / 32; i++) {
            int idx = tid + i * 256;
            int r = idx >> 3, c = idx & 7;
            size_t g = (size_t)(bn + r) * KTOT + kc * 64 + c * 8;
            *(uint4*)(smem + BH + r * ROWB + c * 16) = *(const uint4*)&Bhi[g];
            *(uint4*)(smem + BL + r * ROWB + c * 16) = *(const uint4*)&Blo[g];
        }
        __syncthreads();

#pragma unroll
        for (int kk = 0; kk < 4; kk++) {
            unsigned ah[2][4], al[2][4], bb[NA][2];
#pragma unroll
            for (int i = 0; i < 2; i++) {
                uint32_t ad = sb + (wr * 32 + i * 16 + a_row) * ROWB
                            + (kk * 16 + a_col) * 2;
                ldm_x4(ah[i], ad + AH);
                ldm_x4(al[i], ad + AL);
            }
            // ---- sub-pass 1: B-hi fragments
#pragma unroll
            for (int p = 0; p < NA / 2; p++) {
                uint32_t bd = sb + (wc * WN + p * 16 + b_row) * ROWB
                            + (kk * 16 + b_col) * 2;
                unsigned t[4];
                ldm_x4(t, bd + BH);
                bb[2 * p][0] = t[0]; bb[2 * p][1] = t[1];
                bb[2 * p + 1][0] = t[2]; bb[2 * p + 1][1] = t[3];
            }
#pragma unroll
            for (int i = 0; i < 2; i++)
#pragma unroll
                for (int j = 0; j < NA; j++) {
                    mma16816(acc[i][j], ah[i], bb[j]);
                    mma16816(acc[i][j], al[i], bb[j]);
                }
            // ---- sub-pass 2: B-lo fragments (reuse bb registers)
#pragma unroll
            for (int p = 0; p < NA / 2; p++) {
                uint32_t bd = sb + (wc * WN + p * 16 + b_row) * ROWB
                            + (kk * 16 + b_col) * 2;
                unsigned t[4];
                ldm_x4(t, bd + BL);
                bb[2 * p][0] = t[0]; bb[2 * p][1] = t[1];
                bb[2 * p + 1][0] = t[2]; bb[2 * p + 1][1] = t[3];
            }
#pragma unroll
            for (int i = 0; i < 2; i++)
#pragma unroll
                for (int j = 0; j < NA; j++)
                    mma16816(acc[i][j], ah[i], bb[j]);
        }
        __syncthreads();
    }

#pragma unroll
    for (int i = 0; i < 2; i++) {
        int row = bm + wr * 32 + i * 16 + (lane >> 2);
#pragma unroll
        for (int j = 0; j < NA; j++) {
            int col = bn + wc * WN + j * 8 + (lane & 3) * 2;
            if (row < M)
                *(float2*)&C[(size_t)row * NTOT + col] =
                    make_float2(acc[i][j][0], acc[i][j][1]);
            if (row + 8 < M)
                *(float2*)&C[(size_t)(row + 8) * NTOT + col] =
                    make_float2(acc[i][j][2], acc[i][j][3]);
        }
    }

    if constexpr (FELR) {
        const int head = blockIdx.y * 2 + wc;
        float2 alv[NA], arv[NA];
#pragma unroll
        for (int j = 0; j < NA; j++) {
            int col = bn + wc * WN + j * 8 + (lane & 3) * 2;
            alv[j] = *(const float2*)&alv_g[col];
            arv[j] = *(const float2*)&arv_g[col];
        }
#pragma unroll
        for (int i = 0; i < 2; i++) {
            float el0 = 0.f, el8 = 0.f, er0 = 0.f, er8 = 0.f;
#pragma unroll
            for (int j = 0; j < NA; j++) {
                el0 += acc[i][j][0] * alv[j].x + acc[i][j][1] * alv[j].y;
                er0 += acc[i][j][0] * arv[j].x + acc[i][j][1] * arv[j].y;
                el8 += acc[i][j][2] * alv[j].x + acc[i][j][3] * alv[j].y;
                er8 += acc[i][j][2] * arv[j].x + acc[i][j][3] * arv[j].y;
            }
#pragma unroll
            for (int o = 1; o < 4; o <<= 1) {
                el0 += __shfl_xor_sync(0xFFFFFFFFu, el0, o);
                el8 += __shfl_xor_sync(0xFFFFFFFFu, el8, o);
                er0 += __shfl_xor_sync(0xFFFFFFFFu, er0, o);
                er8 += __shfl_xor_sync(0xFFFFFFFFu, er8, o);
            }
            int row = bm + wr * 32 + i * 16 + (lane >> 2);
            if ((lane & 3) == 0) {
                if (row < M) {
                    g_el1[row * 4 + head] = el0;
                    g_er1[row * 4 + head] = er0;
                }
                if (row + 8 < M) {
                    g_el1[(row + 8) * 4 + head] = el8;
                    g_er1[(row + 8) * 4 + head] = er8;
                }
            }
        }
    }

    if constexpr (FELR2) {
        float* pe = (float*)smem;
        float2 alv[NA], arv[NA];
#pragma unroll
        for (int j = 0; j < NA; j++) {
            int col = wc * WN + j * 8 + (lane & 3) * 2;
            alv[j] = *(const float2*)&alv_g[col];
            arv[j] = *(const float2*)&arv_g[col];
        }
#pragma unroll
        for (int i = 0; i < 2; i++) {
            float el0 = 0.f, el8 = 0.f, er0 = 0.f, er8 = 0.f;
#pragma unroll
            for (int j = 0; j < NA; j++) {
                el0 += acc[i][j][0] * alv[j].x + acc[i][j][1] * alv[j].y;
                er0 += acc[i][j][0] * arv[j].x + acc[i][j][1] * arv[j].y;
                el8 += acc[i][j][2] * alv[j].x + acc[i][j][3] * alv[j].y;
                er8 += acc[i][j][2] * arv[j].x + acc[i][j][3] * arv[j].y;
            }
#pragma unroll
            for (int o = 1; o < 4; o <<= 1) {
                el0 += __shfl_xor_sync(0xFFFFFFFFu, el0, o);
                el8 += __shfl_xor_sync(0xFFFFFFFFu, el8, o);
                er0 += __shfl_xor_sync(0xFFFFFFFFu, er0, o);
                er8 += __shfl_xor_sync(0xFFFFFFFFu, er8, o);
            }
            if ((lane & 3) == 0) {
                int lr = wr * 32 + i * 16 + (lane >> 2);
                pe[wc * 128 + lr]             = el0;
                pe[wc * 128 + lr + 8]         = el8;
                pe[256 + wc * 128 + lr]       = er0;
                pe[256 + wc * 128 + lr + 8]   = er8;
            }
        }
        __syncthreads();
        if (tid < 128) {
            int row = bm + tid;
            if (row < M) {
                g_el2[row] = pe[tid] + pe[128 + tid];
                g_er2[row] = pe[256 + tid] + pe[384 + tid];
            }
        }
    }
}

// ----- layer-1 aggregation: warp per dst, single-pass, 2-way gather ----------
__global__ void agg1_kernel(const float* __restrict__ b1) {
    __shared__ float sm_a[8][128];
    __shared__ int   sm_s[8][32];
    const int wid = threadIdx.x >> 5;
    const int lane = threadIdx.x & 31;
    const int d = blockIdx.x * 8 + wid;
    if (d >= N_NODES) return;
    const int start = g_cnt[d];
    const int end   = g_cnt[d + 1];

    float4 er = *(const float4*)&g_er1[d * 4];
    const int hh = lane >> 3;

    float m0 = -INFINITY, m1 = -INFINITY, m2 = -INFINITY, m3 = -INFINITY;
    float q0 = 0.f, q1 = 0.f, q2 = 0.f, q3 = 0.f;
    float acc0 = 0.f, acc1 = 0.f, acc2 = 0.f, acc3 = 0.f;
    float acc4 = 0.f, acc5 = 0.f, acc6 = 0.f, acc7 = 0.f;

    for (int base = start; base < end; base += 32) {
        int ei = base + lane;
        float e0 = -INFINITY, e1 = -INFINITY, e2 = -INFINITY, e3 = -INFINITY;
        if (ei < end) {
            int s = g_csr_src[ei];
            float4 el = *(const float4*)&g_el1[s * 4];
            e0 = lrelu(el.x + er.x);
            e1 = lrelu(el.y + er.y);
            e2 = lrelu(el.z + er.z);
            e3 = lrelu(el.w + er.w);
            sm_s[wid][lane] = s;
        }
        float n0 = fmaxf(m0, warp_max(e0));
        float n1 = fmaxf(m1, warp_max(e1));
        float n2 = fmaxf(m2, warp_max(e2));
        float n3 = fmaxf(m3, warp_max(e3));
        float r0 = (m0 >= n0) ? 1.f : __expf(m0 - n0);
        float r1 = (m1 >= n1) ? 1.f : __expf(m1 - n1);
        float r2 = (m2 >= n2) ? 1.f : __expf(m2 - n2);
        float r3 = (m3 >= n3) ? 1.f : __expf(m3 - n3);
        float w0 = __expf(e0 - n0);
        float w1 = __expf(e1 - n1);
        float w2 = __expf(e2 - n2);
        float w3 = __expf(e3 - n3);
        m0 = n0; m1 = n1; m2 = n2; m3 = n3;
        q0 = q0 * r0 + w0;
        q1 = q1 * r1 + w1;
        q2 = q2 * r2 + w2;
        q3 = q3 * r3 + w3;
        sm_a[wid][lane * 4 + 0] = w0;
        sm_a[wid][lane * 4 + 1] = w1;
        sm_a[wid][lane * 4 + 2] = w2;
        sm_a[wid][lane * 4 + 3] = w3;
        __syncwarp();
        float rf = (hh == 0) ? r0 : (hh == 1) ? r1 : (hh == 2) ? r2 : r3;
        acc0 *= rf; acc1 *= rf; acc2 *= rf; acc3 *= rf;
        acc4 *= rf; acc5 *= rf; acc6 *= rf; acc7 *= rf;
        int cnt = min(32, end - base);
        int j = 0;
        for (; j + 2 <= cnt; j += 2) {
            int s0 = sm_s[wid][j];
            int s1 = sm_s[wid][j + 1];
            float a0 = sm_a[wid][(j << 2) | hh];
            float a1 = sm_a[wid][((j + 1) << 2) | hh];
            const float4* fp0 = (const float4*)&g_f1[(size_t)s0 * F1DIM + lane * 8];
            const float4* fp1 = (const float4*)&g_f1[(size_t)s1 * F1DIM + lane * 8];
            float4 u0 = fp0[0], v0 = fp0[1];
            float4 u1 = fp1[0], v1 = fp1[1];
            acc0 += a0 * u0.x; acc1 += a0 * u0.y; acc2 += a0 * u0.z; acc3 += a0 * u0.w;
            acc4 += a0 * v0.x; acc5 += a0 * v0.y; acc6 += a0 * v0.z; acc7 += a0 * v0.w;
            acc0 += a1 * u1.x; acc1 += a1 * u1.y; acc2 += a1 * u1.z; acc3 += a1 * u1.w;
            acc4 += a1 * v1.x; acc5 += a1 * v1.y; acc6 += a1 * v1.z; acc7 += a1 * v1.w;
        }
        if (j < cnt) {
            int s = sm_s[wid][j];
            float a = sm_a[wid][(j << 2) | hh];
            const float4* fp = (const float4*)&g_f1[(size_t)s * F1DIM + lane * 8];
            float4 u = fp[0], v = fp[1];
            acc0 += a * u.x; acc1 += a * u.y; acc2 += a * u.z; acc3 += a * u.w;
            acc4 += a * v.x; acc5 += a * v.y; acc6 += a * v.z; acc7 += a * v.w;
        }
        __syncwarp();
    }

    q0 = warp_sum(q0); q1 = warp_sum(q1); q2 = warp_sum(q2); q3 = warp_sum(q3);
    float qs = (hh == 0) ? q0 : (hh == 1) ? q1 : (hh == 2) ? q2 : q3;
    float iv = qs > 0.f ? 1.0f / qs : 0.f;
    acc0 *= iv; acc1 *= iv; acc2 *= iv; acc3 *= iv;
    acc4 *= iv; acc5 *= iv; acc6 *= iv; acc7 *= iv;

    const float* bp = b1 + lane * 8;
    float o[8] = {acc0 + bp[0], acc1 + bp[1], acc2 + bp[2], acc3 + bp[3],
                  acc4 + bp[4], acc5 + bp[5], acc6 + bp[6], acc7 + bp[7]};
#pragma unroll
    for (int c = 0; c < 8; c++) o[c] = o[c] > 0.f ? o[c] : expm1f(o[c]);

    unsigned hv[4], lv[4];
#pragma unroll
    for (int p = 0; p < 4; p++) {
        __nv_bfloat16 h0 = __float2bfloat16(o[2 * p]);
        __nv_bfloat16 h1b = __float2bfloat16(o[2 * p + 1]);
        hv[p] = pk2(h0, h1b);
        lv[p] = pk2(__float2bfloat16(o[2 * p]     - __bfloat162float(h0)),
                    __float2bfloat16(o[2 * p + 1] - __bfloat162float(h1b)));
    }
    size_t off = (size_t)d * F1DIM + lane * 8;
    *(uint4*)&g_h1hi[off] = make_uint4(hv[0], hv[1], hv[2], hv[3]);
    *(uint4*)&g_h1lo[off] = make_uint4(lv[0], lv[1], lv[2], lv[3]);
}

// ----- layer-2 aggregation: warp per dst, single-pass, 4-way gather ----------
__global__ void agg2_kernel(const float* __restrict__ b2,
                            float* __restrict__ out) {
    __shared__ float sm_a[8][32];
    __shared__ int   sm_s[8][32];
    const int wid = threadIdx.x >> 5;
    const int lane = threadIdx.x & 31;
    const int d = blockIdx.x * 8 + wid;
    if (d >= N_NODES) return;
    const int start = g_cnt[d];
    const int end   = g_cnt[d + 1];

    float er = g_er2[d];
    float m = -INFINITY, q = 0.f;
    float accx = 0.f, accy = 0.f;

    for (int base = start; base < end; base += 32) {
        int ei = base + lane;
        float e = -INFINITY;
        if (ei < end) {
            int s = g_csr_src[ei];
            e = lrelu(g_el2[s] + er);
            sm_s[wid][lane] = s;
        }
        float n = fmaxf(m, warp_max(e));
        float r = (m >= n) ? 1.f : __expf(m - n);
        float w = __expf(e - n);
        m = n;
        q = q * r + w;
        sm_a[wid][lane] = w;
        __syncwarp();
        accx *= r; accy *= r;
        int cnt = min(32, end - base);
        int j = 0;
        for (; j + 4 <= cnt; j += 4) {
            int s0 = sm_s[wid][j],     s1 = sm_s[wid][j + 1];
            int s2 = sm_s[wid][j + 2], s3 = sm_s[wid][j + 3];
            float a0 = sm_a[wid][j],     a1 = sm_a[wid][j + 1];
            float a2 = sm_a[wid][j + 2], a3 = sm_a[wid][j + 3];
            float2 f0 = *(const float2*)&g_f2[(size_t)s0 * OUTD + lane * 2];
            float2 f1 = *(const float2*)&g_f2[(size_t)s1 * OUTD + lane * 2];
            float2 f2 = *(const float2*)&g_f2[(size_t)s2 * OUTD + lane * 2];
            float2 f3 = *(const float2*)&g_f2[(size_t)s3 * OUTD + lane * 2];
            accx += a0 * f0.x; accy += a0 * f0.y;
            accx += a1 * f1.x; accy += a1 * f1.y;
            accx += a2 * f2.x; accy += a2 * f2.y;
            accx += a3 * f3.x; accy += a3 * f3.y;
        }
        for (; j < cnt; j++) {
            int s = sm_s[wid][j];
            float a = sm_a[wid][j];
            float2 f = *(const float2*)&g_f2[(size_t)s * OUTD + lane * 2];
            accx += a * f.x;
            accy += a * f.y;
        }
        __syncwarp();
    }

    q = warp_sum(q);
    float iv = q > 0.f ? 1.0f / q : 0.f;
    float2 o = make_float2(accx * iv + b2[lane * 2],
                           accy * iv + b2[lane * 2 + 1]);
    *(float2*)&out[(size_t)d * OUTD + lane * 2] = o;
}

// ------------------------------ launch --------------------------------------
extern "C" void kernel_launch(void* const* d_in, const int* in_sizes, int n_in,
                              void* d_out, int out_size) {
    const float* features = (const float*)d_in[0];
    const float* W1  = (const float*)d_in[1];
    const float* al1 = (const float*)d_in[2];
    const float* ar1 = (const float*)d_in[3];
    const float* b1  = (const float*)d_in[4];
    const float* W2  = (const float*)d_in[5];
    const float* al2 = (const float*)d_in[6];
    const float* ar2 = (const float*)d_in[7];
    const float* b2  = (const float*)d_in[8];
    const int*   src = (const int*)d_in[9];
    const int*   dst = (const int*)d_in[10];
    float* out = (float*)d_out;

    float *p_f1, *p_f2;
    __nv_bfloat16 *p_a1hi, *p_a1lo, *p_h1hi, *p_h1lo;
    __nv_bfloat16 *p_w1hi, *p_w1lo, *p_w2hi, *p_w2lo;
    cudaGetSymbolAddress((void**)&p_f1,   g_f1);
    cudaGetSymbolAddress((void**)&p_f2,   g_f2);
    cudaGetSymbolAddress((void**)&p_a1hi, g_a1hi);
    cudaGetSymbolAddress((void**)&p_a1lo, g_a1lo);
    cudaGetSymbolAddress((void**)&p_h1hi, g_h1hi);
    cudaGetSymbolAddress((void**)&p_h1lo, g_h1lo);
    cudaGetSymbolAddress((void**)&p_w1hi, g_w1hi);
    cudaGetSymbolAddress((void**)&p_w1lo, g_w1lo);
    cudaGetSymbolAddress((void**)&p_w2hi, g_w2hi);
    cudaGetSymbolAddress((void**)&p_w2lo, g_w2lo);

    constexpr int SMEM1 = (2 * 128 + 2 * 128) * 144;  // 73728
    constexpr int SMEM2 = (2 * 128 + 2 * 64) * 144;   // 55296
    cudaFuncSetAttribute((gemm_mma<128, 512, true, false>),
                         cudaFuncAttributeMaxDynamicSharedMemorySize, SMEM1);
    cudaFuncSetAttribute((gemm_mma<64, 256, false, true>),
                         cudaFuncAttributeMaxDynamicSharedMemorySize, SMEM2);

    const int MTILES = (N_NODES + 127) / 128;  // 391

    cudaStream_t s2;
    cudaStreamCreateWithFlags(&s2, cudaStreamNonBlocking);
    cudaEvent_t evFork, evJoin;
    cudaEventCreateWithFlags(&evFork, cudaEventDisableTiming);
    cudaEventCreateWithFlags(&evJoin, cudaEventDisableTiming);

    cudaEventRecord(evFork, 0);
    cudaStreamWaitEvent(s2, evFork, 0);

    // ---- chain A enqueued first (GEMM1 = 4th launch for ncu capture)
    wsplit_kernel<<<(IN_DIM * F1DIM + 255) / 256, 256>>>(W1, p_w1hi, p_w1lo, IN_DIM, F1DIM);
    wsplit_kernel<<<(F1DIM * OUTD + 255) / 256, 256>>>(W2, p_w2hi, p_w2lo, F1DIM, OUTD);
    asplit_kernel<<<(N_NODES * IN_DIM / 4 + 255) / 256, 256>>>(
        features, p_a1hi, p_a1lo, N_NODES * IN_DIM / 4);
    {
        dim3 grid(MTILES, F1DIM / 128);
        gemm_mma<128, 512, true, false><<<grid, 256, SMEM1>>>(
            p_a1hi, p_a1lo, p_w1hi, p_w1lo, p_f1, N_NODES, F1DIM, al1, ar1);
    }

    // ---- chain B on s2: CSR build
    init_kernel<<<(N_NODES + 256) / 256, 256, 0, s2>>>();
    hist_kernel<<<(N_EDGES + 255) / 256, 256, 0, s2>>>(dst);
    scanA_kernel<<<SCAN_NB, 256, 0, s2>>>();
    scanB_kernel<<<1, 256, 0, s2>>>();
    scanC_kernel<<<SCAN_NB, 256, 0, s2>>>();
    fill_kernel<<<(N_EDGES + 255) / 256, 256, 0, s2>>>(src, dst);

    // join
    cudaEventRecord(evJoin, s2);
    cudaStreamWaitEvent(0, evJoin, 0);

    // ---- serial tail
    agg1_kernel<<<(N_NODES + 7) / 8, 256>>>(b1);
    {
        dim3 grid(MTILES, 1);
        gemm_mma<64, 256, false, true><<<grid, 256, SMEM2>>>(
            p_h1hi, p_h1lo, p_w2hi, p_w2lo, p_f2, N_NODES, OUTD, al2, ar2);
    }
    agg2_kernel<<<(N_NODES + 7) / 8, 256>>>(b2, out);
}